// round 7
// baseline (speedup 1.0000x reference)
#include <cuda_runtime.h>
#include <cuda_bf16.h>
#include <cstdint>

#define BB 4096
#define MM 327
#define NN 800
#define NB (BB*NN)              // 3,276,800 per state buffer
#define NROWS 968               // 22*44 padded pixel rows
#define NHWC_STRIDE (NROWS*32)  // floats per image in NHWC buffers
#define SROW0 48
#define SROWS 1088              // 48 + 992 + 48 guard rows
#define ASTRIDE 17              // words per row in smem A (16 pairs + 1 pad)
#define BSTRIDE 34              // words per icpair in smem B (32 oc + 2 pad)
#define BWORDS (9*16*BSTRIDE)   // 4896 words per (set,half)

typedef unsigned long long ull;

// ---------------- device scratch (static, allowed) ----------------
__device__ float g_PhiTPhi[NN*NN];
__device__ float g_PhiTb[NB];
__device__ float g_Xbuf[2*NB];
__device__ float g_Lbuf[2*NB];
__device__ float g_zerobuf[NB];
__device__ float g_zflat[NB];
__device__ float g_hatx[NB];
__device__ float g_gemm[NB];
__device__ float g_nA[(size_t)BB*NHWC_STRIDE];   // NHWC feature buffer A
__device__ float g_nB[(size_t)BB*NHWC_STRIDE];   // NHWC feature buffer B
__device__ uint32_t g_wpk[2*2*BWORDS];           // [set][hi/lo][4896] packed bf16x2

// ---------------- helpers ----------------
__device__ __forceinline__ uint32_t pkbf2(__nv_bfloat16 e0, __nv_bfloat16 e1) {
    return ((uint32_t)__bfloat16_as_ushort(e1) << 16) | (uint32_t)__bfloat16_as_ushort(e0);
}

__device__ __forceinline__ void mma_bf16(float* d, const uint32_t* a, uint32_t b0, uint32_t b1) {
    asm volatile(
        "mma.sync.aligned.m16n8k16.row.col.f32.bf16.bf16.f32 "
        "{%0,%1,%2,%3}, {%4,%5,%6,%7}, {%8,%9}, {%0,%1,%2,%3};"
        : "+f"(d[0]), "+f"(d[1]), "+f"(d[2]), "+f"(d[3])
        : "r"(a[0]), "r"(a[1]), "r"(a[2]), "r"(a[3]), "r"(b0), "r"(b1));
}

// ---------------- small GEMMs (proven R4 versions) ----------------

__global__ __launch_bounds__(256) void gemm_AtB(const float* __restrict__ A,
                                                const float* __restrict__ B,
                                                float* __restrict__ C,
                                                int K, int I, int J)
{
    __shared__ float As[16][68];
    __shared__ float Bs[16][68];
    int tid = threadIdx.x;
    int tx = tid & 15, ty = tid >> 4;
    int i0 = blockIdx.y * 64, j0 = blockIdx.x * 64;
    float acc[4][4];
#pragma unroll
    for (int a = 0; a < 4; a++)
#pragma unroll
        for (int b = 0; b < 4; b++) acc[a][b] = 0.f;

    int kr = tid >> 4, c4 = (tid & 15) * 4;
    for (int k0 = 0; k0 < K; k0 += 16) {
        bool kv = (k0 + kr) < K;
#pragma unroll
        for (int j = 0; j < 4; j++) {
            int ii = i0 + c4 + j;
            As[kr][c4 + j] = (kv && ii < I) ? A[(size_t)(k0 + kr) * I + ii] : 0.f;
            int jj = j0 + c4 + j;
            Bs[kr][c4 + j] = (kv && jj < J) ? B[(size_t)(k0 + kr) * J + jj] : 0.f;
        }
        __syncthreads();
#pragma unroll
        for (int kk = 0; kk < 16; kk++) {
            float a[4], b[4];
#pragma unroll
            for (int i = 0; i < 4; i++) a[i] = As[kk][ty * 4 + i];
#pragma unroll
            for (int j = 0; j < 4; j++) b[j] = Bs[kk][tx * 4 + j];
#pragma unroll
            for (int i = 0; i < 4; i++)
#pragma unroll
                for (int j = 0; j < 4; j++) acc[i][j] += a[i] * b[j];
        }
        __syncthreads();
    }
#pragma unroll
    for (int i = 0; i < 4; i++) {
        int r = i0 + ty * 4 + i;
        if (r < I) {
#pragma unroll
            for (int j = 0; j < 4; j++) {
                int n = j0 + tx * 4 + j;
                if (n < J) C[(size_t)r * J + n] = acc[i][j];
            }
        }
    }
}

__global__ __launch_bounds__(256) void gemm_AB(const float* __restrict__ A,
                                               const float* __restrict__ B,
                                               float* __restrict__ C,
                                               int M, int K, int N)
{
    __shared__ float As[16][132];
    __shared__ float Bs[16][68];
    int tid = threadIdx.x;
    int tx = tid & 15, ty = tid >> 4;
    int row0 = blockIdx.y * 128, n0 = blockIdx.x * 64;

    float acc[8][4];
#pragma unroll
    for (int a = 0; a < 8; a++)
#pragma unroll
        for (int b = 0; b < 4; b++) acc[a][b] = 0.f;

    int arow = tid >> 1;
    int ak0 = (tid & 1) * 8;
    int kr = tid >> 4, nc = (tid & 15) * 4;

    for (int k0 = 0; k0 < K; k0 += 16) {
        const float* aptr = A + (size_t)(row0 + arow) * K + k0 + ak0;
#pragma unroll
        for (int j = 0; j < 8; j++) {
            int k = k0 + ak0 + j;
            As[ak0 + j][arow] = (k < K) ? aptr[j] : 0.f;
        }
#pragma unroll
        for (int j = 0; j < 4; j++) {
            int n = n0 + nc + j;
            Bs[kr][nc + j] = ((k0 + kr) < K && n < N) ? B[(size_t)(k0 + kr) * N + n] : 0.f;
        }
        __syncthreads();
#pragma unroll
        for (int kk = 0; kk < 16; kk++) {
            float a[8], b[4];
#pragma unroll
            for (int i = 0; i < 8; i++) a[i] = As[kk][ty * 8 + i];
#pragma unroll
            for (int j = 0; j < 4; j++) b[j] = Bs[kk][tx * 4 + j];
#pragma unroll
            for (int i = 0; i < 8; i++)
#pragma unroll
                for (int j = 0; j < 4; j++) acc[i][j] += a[i] * b[j];
        }
        __syncthreads();
    }
#pragma unroll
    for (int i = 0; i < 8; i++) {
        int r = row0 + ty * 8 + i;
#pragma unroll
        for (int j = 0; j < 4; j++) {
            int n = n0 + tx * 4 + j;
            if (n < N) C[(size_t)r * N + n] = acc[i][j];
        }
    }
}

__global__ void k_wloss(const float* __restrict__ W, float* __restrict__ C)
{
    __shared__ float sA[16][17];
    __shared__ float sB[16][17];
    int tx = threadIdx.x, ty = threadIdx.y;
    int i0 = blockIdx.y * 16, j0 = blockIdx.x * 16;
    float acc = 0.f;
    for (int k0 = 0; k0 < 800; k0 += 16) {
        sA[ty][tx] = (i0 + ty < MM) ? W[(size_t)(i0 + ty) * NN + k0 + tx] : 0.f;
        sB[ty][tx] = (j0 + ty < MM) ? W[(size_t)(j0 + ty) * NN + k0 + tx] : 0.f;
        __syncthreads();
#pragma unroll
        for (int kk = 0; kk < 16; kk++) acc += sA[ty][kk] * sB[tx][kk];
        __syncthreads();
    }
    int i = i0 + ty, j = j0 + tx;
    if (i < MM && j < MM) C[i * MM + j] = acc - (i == j ? 1.f : 0.f);
}

// ---------------- elementwise ----------------

__global__ void k_layer0(const float* __restrict__ PhiTb, float* __restrict__ X1,
                         float* __restrict__ zf,
                         const float* __restrict__ h_arr, const float* __restrict__ b2_arr)
{
    int i = blockIdx.x * blockDim.x + threadIdx.x;
    if (i >= NB) return;
    float h0 = h_arr[0], b2 = b2_arr[0];
    float x = h0 * PhiTb[i];
    X1[i] = x;
    zf[i] = h0 * b2 * x;
}

__global__ void k_hatx(const float* __restrict__ Xc, const float* __restrict__ Xp,
                       float* __restrict__ hx,
                       const float* __restrict__ tx_arr, int layer)
{
    int i = blockIdx.x * blockDim.x + threadIdx.x;
    if (i >= NB) return;
    float t = tx_arr[layer];
    float xc = Xc[i];
    hx[i] = xc + t * (xc - Xp[i]);
}

__global__ void k_xepi(const float* __restrict__ hx, const float* __restrict__ gm,
                       const float* __restrict__ PhiTb,
                       const float* __restrict__ Zg, const float* __restrict__ Lg,
                       const float* __restrict__ Zc, const float* __restrict__ Zp,
                       const float* __restrict__ Lz,
                       float* __restrict__ Xn, float* __restrict__ zf,
                       const float* __restrict__ b1a, const float* __restrict__ b2a,
                       const float* __restrict__ ha, const float* __restrict__ tza,
                       int layer)
{
    int i = blockIdx.x * blockDim.x + threadIdx.x;
    if (i >= NB) return;
    float b1 = b1a[layer], b2 = b2a[layer], hh = ha[layer], tz = tza[layer];
    float hxv = hx[i];
    float grad = PhiTb[i] - gm[i] + b1 * (Zg[i] - hxv) - Lg[i];
    float xn = hxv + hh * grad;
    Xn[i] = xn;
    float zc = Zc[i];
    float hz = zc + tz * (zc - Zp[i]);
    zf[i] = hz + hh * (Lz[i] + b2 * (xn - hz));
}

// ---------------- setup kernels ----------------

// zero the padding rows (r=0, r=21, c=0, c=43) of both NHWC buffers.
__global__ __launch_bounds__(128) void k_zeropad(float* __restrict__ a, float* __restrict__ b)
{
    int img = blockIdx.x, t = threadIdx.x;
    int row;
    if (t < 44) row = t;
    else if (t < 88) row = 924 + (t - 44);
    else { int j = t - 88; row = (1 + (j >> 1)) * 44 + ((j & 1) ? 43 : 0); }
    float4 z = make_float4(0.f, 0.f, 0.f, 0.f);
    float4* pa = (float4*)(a + (size_t)img * NHWC_STRIDE + row * 32);
    float4* pb = (float4*)(b + (size_t)img * NHWC_STRIDE + row * 32);
#pragma unroll
    for (int q = 0; q < 8; q++) { pa[q] = z; pb[q] = z; }
}

// weights [oc][ic][3][3] -> packed bf16 hi/lo [set][half][tap][icpair][BSTRIDE]
__global__ void k_wbf(const float* __restrict__ c2f, const float* __restrict__ c1b,
                      uint32_t* __restrict__ wpk)
{
    int i = blockIdx.x * blockDim.x + threadIdx.x;
    if (i >= 2 * BWORDS) return;
    int set = i / BWORDS, rem = i - set * BWORDS;
    int tap = rem / (16 * BSTRIDE), rem2 = rem - tap * (16 * BSTRIDE);
    int icp = rem2 / BSTRIDE, oc = rem2 - icp * BSTRIDE;
    const float* src = set ? c1b : c2f;
    uint32_t whi = 0u, wlo = 0u;
    if (oc < 32) {
        float w0 = src[oc * 288 + (2 * icp) * 9 + tap];
        float w1 = src[oc * 288 + (2 * icp + 1) * 9 + tap];
        __nv_bfloat16 h0 = __float2bfloat16_rn(w0), h1 = __float2bfloat16_rn(w1);
        __nv_bfloat16 l0 = __float2bfloat16_rn(w0 - __bfloat162float(h0));
        __nv_bfloat16 l1 = __float2bfloat16_rn(w1 - __bfloat162float(h1));
        whi = pkbf2(h0, h1);
        wlo = pkbf2(l0, l1);
    }
    int off = tap * (16 * BSTRIDE) + icp * BSTRIDE + oc;
    wpk[set * 2 * BWORDS + off] = whi;
    wpk[set * 2 * BWORDS + BWORDS + off] = wlo;
}

// ---------------- convolutions ----------------

// 1->32 channels, 3x3 SAME, relu. HW input -> NHWC output. One block per image.
__global__ __launch_bounds__(256) void conv1to32_nhwc(const float* __restrict__ zf,
                                                      const float* __restrict__ w,
                                                      float* __restrict__ out)
{
    __shared__ float sZ[NROWS];
    __shared__ float sW[288];    // [tap][oc]
    int img = blockIdx.x, tid = threadIdx.x;
    for (int i = tid; i < NROWS; i += 256) sZ[i] = 0.f;
    for (int i = tid; i < 288; i += 256) {
        int oc = i / 9, tap = i - oc * 9;
        sW[tap * 32 + oc] = w[i];
    }
    __syncthreads();
    const float* gin = zf + (size_t)img * NN;
    for (int i = tid; i < NN; i += 256) {
        int r = i / 40, c = i - r * 40;
        sZ[(r + 1) * 44 + c + 1] = gin[i];
    }
    __syncthreads();
    const int dtap[9] = {-45, -44, -43, -1, 0, 1, 43, 44, 45};
    float* gout = out + (size_t)img * NHWC_STRIDE;
    for (int p = tid; p < NN; p += 256) {
        int r = p / 40, c = p - r * 40;
        int pp = (r + 1) * 44 + (c + 1);
        float acc[32];
#pragma unroll
        for (int oc = 0; oc < 32; oc++) acc[oc] = 0.f;
#pragma unroll
        for (int t = 0; t < 9; t++) {
            float xv = sZ[pp + dtap[t]];
            const float* wt = sW + t * 32;
#pragma unroll
            for (int oc = 0; oc < 32; oc++) acc[oc] += wt[oc] * xv;
        }
        float4* ob = (float4*)(gout + pp * 32);
#pragma unroll
        for (int q = 0; q < 8; q++) {
            float4 v = make_float4(fmaxf(acc[q*4+0], 0.f), fmaxf(acc[q*4+1], 0.f),
                                   fmaxf(acc[q*4+2], 0.f), fmaxf(acc[q*4+3], 0.f));
            ob[q] = v;
        }
    }
}

// 32->32 channels, 3x3 SAME via mma.sync bf16 (3-pass hi/lo split).
// NHWC fp32 in/out. One CTA per image, 256 threads (8 warps).
__global__ __launch_bounds__(256) void conv32_mma(const float* __restrict__ in,
                                                  const uint32_t* __restrict__ wpk,
                                                  float* __restrict__ outp,
                                                  const float* __restrict__ thr_arr,
                                                  int layer, int do_soft, int do_relu)
{
    extern __shared__ uint32_t smw[];
    uint32_t* sAhi = smw;                       // SROWS*ASTRIDE
    uint32_t* sAlo = smw + SROWS * ASTRIDE;
    uint32_t* sBhi = smw + 2 * SROWS * ASTRIDE; // BWORDS
    uint32_t* sBlo = sBhi + BWORDS;
    int img = blockIdx.x, tid = threadIdx.x;

    // zero guard rows [0,48) and [1016,1088)
    for (int i = tid; i < 48 * ASTRIDE; i += 256) { sAhi[i] = 0u; sAlo[i] = 0u; }
    for (int i = tid; i < 72 * ASTRIDE; i += 256) {
        sAhi[1016 * ASTRIDE + i] = 0u; sAlo[1016 * ASTRIDE + i] = 0u;
    }
    // weights
    for (int i = tid; i < BWORDS; i += 256) { sBhi[i] = wpk[i]; sBlo[i] = wpk[BWORDS + i]; }

    // main fill: fp32 NHWC -> (soft) -> bf16 hi/lo packed pairs
    float sthr = do_soft ? fabsf(thr_arr[layer]) : 0.f;
    const float4* g4 = (const float4*)(in + (size_t)img * NHWC_STRIDE);
    for (int i = tid; i < NROWS * 8; i += 256) {
        float4 v = g4[i];
        if (do_soft) {
#pragma unroll
            for (int j = 0; j < 4; j++) {
                float x = (&v.x)[j];
                float a = fabsf(x) - sthr;
                (&v.x)[j] = (a > 0.f) ? (x > 0.f ? a : -a) : 0.f;
            }
        }
        int row = i >> 3, qq = i & 7;
        int base = (SROW0 + row) * ASTRIDE + qq * 2;
        __nv_bfloat16 h0 = __float2bfloat16_rn(v.x);
        __nv_bfloat16 h1 = __float2bfloat16_rn(v.y);
        __nv_bfloat16 h2 = __float2bfloat16_rn(v.z);
        __nv_bfloat16 h3 = __float2bfloat16_rn(v.w);
        __nv_bfloat16 l0 = __float2bfloat16_rn(v.x - __bfloat162float(h0));
        __nv_bfloat16 l1 = __float2bfloat16_rn(v.y - __bfloat162float(h1));
        __nv_bfloat16 l2 = __float2bfloat16_rn(v.z - __bfloat162float(h2));
        __nv_bfloat16 l3 = __float2bfloat16_rn(v.w - __bfloat162float(h3));
        sAhi[base]     = pkbf2(h0, h1);
        sAhi[base + 1] = pkbf2(h2, h3);
        sAlo[base]     = pkbf2(l0, l1);
        sAlo[base + 1] = pkbf2(l2, l3);
    }
    __syncthreads();

    int warp = tid >> 5, lane = tid & 31;
    int q = lane >> 2, c = lane & 3;
    const int dtap[9] = {-45, -44, -43, -1, 0, 1, 43, 44, 45};
    float* gout = outp + (size_t)img * NHWC_STRIDE;

    for (int u = warp; u < 31; u += 8) {
        float acc[2][4][4];
#pragma unroll
        for (int s = 0; s < 2; s++)
#pragma unroll
            for (int o = 0; o < 4; o++)
#pragma unroll
                for (int j = 0; j < 4; j++) acc[s][o][j] = 0.f;

        int base_row = SROW0 + u * 32;
#pragma unroll
        for (int pass = 0; pass < 3; pass++) {
            const uint32_t* Aarr = (pass == 2) ? sAlo : sAhi;
            const uint32_t* Barr = (pass == 1) ? sBlo : sBhi;
#pragma unroll
            for (int ks = 0; ks < 18; ks++) {
                const int tap = ks >> 1;
                const int icb = (ks & 1) * 8;
                const uint32_t* Ap = Aarr + (base_row + dtap[tap] + q) * ASTRIDE + icb + c;
                uint32_t a0[4], a1[4];
                a0[0] = Ap[0];
                a0[1] = Ap[8 * ASTRIDE];
                a0[2] = Ap[4];
                a0[3] = Ap[8 * ASTRIDE + 4];
                a1[0] = Ap[16 * ASTRIDE];
                a1[1] = Ap[24 * ASTRIDE];
                a1[2] = Ap[16 * ASTRIDE + 4];
                a1[3] = Ap[24 * ASTRIDE + 4];
                const uint32_t* Bp = Barr + tap * (16 * BSTRIDE) + (icb + c) * BSTRIDE + q;
#pragma unroll
                for (int o = 0; o < 4; o++) {
                    uint32_t b0 = Bp[o * 8];
                    uint32_t b1 = Bp[4 * BSTRIDE + o * 8];
                    mma_bf16(acc[0][o], a0, b0, b1);
                    mma_bf16(acc[1][o], a1, b0, b1);
                }
            }
        }

        // epilogue: C frag (row=q/q+8, col=2c,2c+1 per octile)
#pragma unroll
        for (int s = 0; s < 2; s++) {
            int grow0 = u * 32 + s * 16 + q;
#pragma unroll
            for (int half = 0; half < 2; half++) {
                int grow = grow0 + half * 8;
                int rr = grow / 44, cc = grow - rr * 44;
                bool valid = (grow < NROWS) && rr >= 1 && rr <= 20 && cc >= 1 && cc <= 40;
                if (valid) {
                    float* ob = gout + grow * 32 + c * 2;
#pragma unroll
                    for (int o = 0; o < 4; o++) {
                        float x0 = acc[s][o][half * 2 + 0];
                        float x1 = acc[s][o][half * 2 + 1];
                        if (do_relu) { x0 = fmaxf(x0, 0.f); x1 = fmaxf(x1, 0.f); }
                        *(float2*)(ob + o * 8) = make_float2(x0, x1);
                    }
                }
            }
        }
    }
}

// 32->1 channels, 3x3 SAME, NHWC input. variant 0: Z_new + fused L-update.
// variant 1: (conv - z_flat) into syms.
__global__ __launch_bounds__(512) void conv32to1_nhwc(const float* __restrict__ in,
                                                      const float* __restrict__ w288,
                                                      float* __restrict__ outp,
                                                      const float* __restrict__ zf,
                                                      float* __restrict__ Ln,
                                                      const float* __restrict__ Lc,
                                                      const float* __restrict__ Lp,
                                                      const float* __restrict__ Xn,
                                                      const float* __restrict__ h_arr,
                                                      const float* __restrict__ b1_arr,
                                                      const float* __restrict__ tL_arr,
                                                      int layer, int variant)
{
    extern __shared__ float smemf[];
    float* sIn = smemf;                 // 968*32
    float* sW  = smemf + NROWS * 32;    // [tap][ic]
    int img = blockIdx.x, tid = threadIdx.x;
    const float4* g4 = (const float4*)(in + (size_t)img * NHWC_STRIDE);
    float4* s4 = (float4*)sIn;
    for (int i = tid; i < NROWS * 8; i += 512) s4[i] = g4[i];
    for (int i = tid; i < 288; i += 512) {
        int ic = i / 9, tap = i - ic * 9;
        sW[tap * 32 + ic] = w288[i];
    }
    __syncthreads();

    const int dtap[9] = {-45, -44, -43, -1, 0, 1, 43, 44, 45};
    size_t base = (size_t)img * NN;
    for (int p = tid; p < NN; p += 512) {
        int r = p / 40, c = p - r * 40;
        int pp = (r + 1) * 44 + (c + 1);
        float acc = 0.f;
#pragma unroll
        for (int t = 0; t < 9; t++) {
            const float4* a4 = (const float4*)(sIn + (pp + dtap[t]) * 32);
            const float4* wv = (const float4*)(sW + t * 32);
#pragma unroll
            for (int qq = 0; qq < 8; qq++) {
                float4 x = a4[qq], ww = wv[qq];
                acc += x.x * ww.x + x.y * ww.y + x.z * ww.z + x.w * ww.w;
            }
        }
        if (variant == 0) {
            outp[base + p] = acc;
            float lc = Lc[base + p], lp = Lp[base + p];
            float hatL = lc + tL_arr[layer] * (lc - lp);
            Ln[base + p] = hatL + h_arr[layer] * b1_arr[layer] * (Xn[base + p] - acc);
        } else {
            outp[base + p] = acc - zf[base + p];
        }
    }
}

// ---------------- host ----------------

extern "C" void kernel_launch(void* const* d_in, const int* in_sizes, int n_in,
                              void* d_out, int out_size)
{
    const float* y    = (const float*)d_in[0];
    const float* W    = (const float*)d_in[2];
    const float* beta1 = (const float*)d_in[3];
    const float* beta2 = (const float*)d_in[4];
    const float* h_   = (const float*)d_in[5];
    const float* sthr = (const float*)d_in[6];
    const float* thx  = (const float*)d_in[7];
    const float* thz  = (const float*)d_in[8];
    const float* thL  = (const float*)d_in[9];
    const float* c1f  = (const float*)d_in[10];
    const float* c2f  = (const float*)d_in[11];
    const float* c1b  = (const float*)d_in[12];
    const float* c2b  = (const float*)d_in[13];

    float* out = (float*)d_out;
    float* Zs = out;
    float* syms = out + (size_t)9 * NB;
    float* wlo = out + (size_t)18 * NB;

    float *pPhiTPhi, *pPhiTb, *pX, *pL, *pZero, *pZf, *pHx, *pGm, *pNA, *pNB;
    uint32_t* pWPK;
    cudaGetSymbolAddress((void**)&pPhiTPhi, g_PhiTPhi);
    cudaGetSymbolAddress((void**)&pPhiTb, g_PhiTb);
    cudaGetSymbolAddress((void**)&pX, g_Xbuf);
    cudaGetSymbolAddress((void**)&pL, g_Lbuf);
    cudaGetSymbolAddress((void**)&pZero, g_zerobuf);
    cudaGetSymbolAddress((void**)&pZf, g_zflat);
    cudaGetSymbolAddress((void**)&pHx, g_hatx);
    cudaGetSymbolAddress((void**)&pGm, g_gemm);
    cudaGetSymbolAddress((void**)&pNA, g_nA);
    cudaGetSymbolAddress((void**)&pNB, g_nB);
    cudaGetSymbolAddress((void**)&pWPK, g_wpk);

    const int SMMAW = (2 * SROWS * ASTRIDE + 2 * BWORDS) * 4;  // 187,136 B
    const int SM1   = (NROWS * 32 + 288) * 4;                  // 125,056 B
    cudaFuncSetAttribute(conv32_mma, cudaFuncAttributeMaxDynamicSharedMemorySize, SMMAW);
    cudaFuncSetAttribute(conv32to1_nhwc, cudaFuncAttributeMaxDynamicSharedMemorySize, SM1);

    cudaMemsetAsync(pZero, 0, (size_t)NB * 4);

    float* Xslot[2] = {pX, pX + NB};
    float* Lslot[2] = {pL, pL + NB};

    // setup
    gemm_AtB<<<dim3(13, 13), 256>>>(W, W, pPhiTPhi, MM, NN, NN);
    k_wloss<<<dim3(21, 21), dim3(16, 16)>>>(W, wlo);
    gemm_AB<<<dim3(13, 32), 256>>>(y, W, pPhiTb, BB, MM, NN);
    k_zeropad<<<BB, 128>>>(pNA, pNB);
    k_wbf<<<(2 * BWORDS + 255) / 256, 256>>>(c2f, c1b, pWPK);

    int xcur = 0, xprev = -1;
    int lcur = 0, lprev = -1;

    for (int i = 0; i < 9; i++) {
        float* Xn;
        if (i == 0) {
            Xn = Xslot[0];
            k_layer0<<<NB / 256, 256>>>(pPhiTb, Xn, pZf, h_, beta2);
            xcur = 0; xprev = -1;
        } else {
            const float* Xc = Xslot[xcur];
            const float* Xp = (xprev < 0) ? pZero : Xslot[xprev];
            const float* Lc_ = Lslot[lcur];
            const float* Zc = Zs + (size_t)(i - 1) * NB;
            const float* Zp = (i >= 2) ? Zs + (size_t)(i - 2) * NB : pZero;
            const float* Zg = (i >= 2) ? Zc : pZero;
            const float* Lg = (i >= 2) ? Lc_ : pZero;
            const float* Lz = (i >= 2) ? Lc_ : pZero;
            int xnew = (xprev < 0) ? 1 : xprev;
            Xn = Xslot[xnew];
            k_hatx<<<NB / 256, 256>>>(Xc, Xp, pHx, thx, i);
            gemm_AB<<<dim3(13, 32), 256>>>(pHx, pPhiTPhi, pGm, BB, NN, NN);
            k_xepi<<<NB / 256, 256>>>(pHx, pGm, pPhiTb, Zg, Lg, Zc, Zp, Lz,
                                      Xn, pZf, beta1, beta2, h_, thz, i);
            xprev = xcur; xcur = xnew;
        }

        // conv block (NHWC domain)
        conv1to32_nhwc<<<BB, 256>>>(pZf, c1f, pNA);
        conv32_mma<<<BB, 256, SMMAW>>>(pNA, pWPK,             pNB, sthr, i, 0, 0); // x_fwd
        conv32_mma<<<BB, 256, SMMAW>>>(pNB, pWPK + 2 * BWORDS, pNA, sthr, i, 1, 1); // t1
        {
            const float* Lc_ = (i == 0) ? pZero : Lslot[lcur];
            const float* Lp_ = (i == 0) ? pZero : ((lprev < 0) ? pZero : Lslot[lprev]);
            int lnew = (i == 0) ? 0 : ((lprev < 0) ? 1 : lprev);
            conv32to1_nhwc<<<BB, 512, SM1>>>(pNA, c2b, Zs + (size_t)i * NB, nullptr,
                                             Lslot[lnew], Lc_, Lp_, Xn,
                                             h_, beta1, thL, i, 0);
            if (i > 0) { lprev = lcur; lcur = lnew; }
            else { lcur = 0; lprev = -1; }
        }
        conv32_mma<<<BB, 256, SMMAW>>>(pNB, pWPK + 2 * BWORDS, pNA, sthr, i, 0, 1); // t2
        conv32to1_nhwc<<<BB, 512, SM1>>>(pNA, c2b, syms + (size_t)i * NB, pZf,
                                         nullptr, nullptr, nullptr, nullptr,
                                         h_, beta1, thL, i, 1);
    }
}

// round 8
// speedup vs baseline: 1.1984x; 1.1984x over previous
#include <cuda_runtime.h>
#include <cuda_bf16.h>
#include <cstdint>

#define BB 4096
#define MM 327
#define NN 800
#define NB (BB*NN)              // 3,276,800 per state buffer
#define NROWS 968               // 22*44 padded pixel rows
#define NHWC_STRIDE (NROWS*32)  // floats per image in NHWC buffers
#define SROW0 48
#define SROWS 1086              // 48 guard + 968 data + 70 guard rows
#define ASTRIDE 20              // words per row in smem A (16 data + 4 pad; 20%32=20 -> {20q+c} distinct)
#define BSTRIDE 40              // words per icpair in smem B (32 oc + 8 pad; {40c+q} distinct)
#define BWORDS (9*16*BSTRIDE)   // 5760 words per (set,half)

typedef unsigned long long ull;

// ---------------- device scratch (static, allowed) ----------------
__device__ float g_PhiTPhi[NN*NN];
__device__ float g_PhiTb[NB];
__device__ float g_Xbuf[2*NB];
__device__ float g_Lbuf[2*NB];
__device__ float g_zerobuf[NB];
__device__ float g_zflat[NB];
__device__ float g_hatx[NB];
__device__ float g_gemm[NB];
__device__ float g_nA[(size_t)BB*NHWC_STRIDE];   // NHWC feature buffer A
__device__ float g_nB[(size_t)BB*NHWC_STRIDE];   // NHWC feature buffer B
__device__ uint32_t g_wpk[2*2*BWORDS];           // [set][hi/lo][BWORDS] packed bf16x2

// ---------------- helpers ----------------
__device__ __forceinline__ uint32_t pkbf2(__nv_bfloat16 e0, __nv_bfloat16 e1) {
    return ((uint32_t)__bfloat16_as_ushort(e1) << 16) | (uint32_t)__bfloat16_as_ushort(e0);
}

__device__ __forceinline__ void mma_bf16(float* d, const uint32_t* a, uint32_t b0, uint32_t b1) {
    asm volatile(
        "mma.sync.aligned.m16n8k16.row.col.f32.bf16.bf16.f32 "
        "{%0,%1,%2,%3}, {%4,%5,%6,%7}, {%8,%9}, {%0,%1,%2,%3};"
        : "+f"(d[0]), "+f"(d[1]), "+f"(d[2]), "+f"(d[3])
        : "r"(a[0]), "r"(a[1]), "r"(a[2]), "r"(a[3]), "r"(b0), "r"(b1));
}

// ---------------- small GEMMs (proven R4 versions) ----------------

__global__ __launch_bounds__(256) void gemm_AtB(const float* __restrict__ A,
                                                const float* __restrict__ B,
                                                float* __restrict__ C,
                                                int K, int I, int J)
{
    __shared__ float As[16][68];
    __shared__ float Bs[16][68];
    int tid = threadIdx.x;
    int tx = tid & 15, ty = tid >> 4;
    int i0 = blockIdx.y * 64, j0 = blockIdx.x * 64;
    float acc[4][4];
#pragma unroll
    for (int a = 0; a < 4; a++)
#pragma unroll
        for (int b = 0; b < 4; b++) acc[a][b] = 0.f;

    int kr = tid >> 4, c4 = (tid & 15) * 4;
    for (int k0 = 0; k0 < K; k0 += 16) {
        bool kv = (k0 + kr) < K;
#pragma unroll
        for (int j = 0; j < 4; j++) {
            int ii = i0 + c4 + j;
            As[kr][c4 + j] = (kv && ii < I) ? A[(size_t)(k0 + kr) * I + ii] : 0.f;
            int jj = j0 + c4 + j;
            Bs[kr][c4 + j] = (kv && jj < J) ? B[(size_t)(k0 + kr) * J + jj] : 0.f;
        }
        __syncthreads();
#pragma unroll
        for (int kk = 0; kk < 16; kk++) {
            float a[4], b[4];
#pragma unroll
            for (int i = 0; i < 4; i++) a[i] = As[kk][ty * 4 + i];
#pragma unroll
            for (int j = 0; j < 4; j++) b[j] = Bs[kk][tx * 4 + j];
#pragma unroll
            for (int i = 0; i < 4; i++)
#pragma unroll
                for (int j = 0; j < 4; j++) acc[i][j] += a[i] * b[j];
        }
        __syncthreads();
    }
#pragma unroll
    for (int i = 0; i < 4; i++) {
        int r = i0 + ty * 4 + i;
        if (r < I) {
#pragma unroll
            for (int j = 0; j < 4; j++) {
                int n = j0 + tx * 4 + j;
                if (n < J) C[(size_t)r * J + n] = acc[i][j];
            }
        }
    }
}

__global__ __launch_bounds__(256) void gemm_AB(const float* __restrict__ A,
                                               const float* __restrict__ B,
                                               float* __restrict__ C,
                                               int M, int K, int N)
{
    __shared__ float As[16][132];
    __shared__ float Bs[16][68];
    int tid = threadIdx.x;
    int tx = tid & 15, ty = tid >> 4;
    int row0 = blockIdx.y * 128, n0 = blockIdx.x * 64;

    float acc[8][4];
#pragma unroll
    for (int a = 0; a < 8; a++)
#pragma unroll
        for (int b = 0; b < 4; b++) acc[a][b] = 0.f;

    int arow = tid >> 1;
    int ak0 = (tid & 1) * 8;
    int kr = tid >> 4, nc = (tid & 15) * 4;

    for (int k0 = 0; k0 < K; k0 += 16) {
        const float* aptr = A + (size_t)(row0 + arow) * K + k0 + ak0;
#pragma unroll
        for (int j = 0; j < 8; j++) {
            int k = k0 + ak0 + j;
            As[ak0 + j][arow] = (k < K) ? aptr[j] : 0.f;
        }
#pragma unroll
        for (int j = 0; j < 4; j++) {
            int n = n0 + nc + j;
            Bs[kr][nc + j] = ((k0 + kr) < K && n < N) ? B[(size_t)(k0 + kr) * N + n] : 0.f;
        }
        __syncthreads();
#pragma unroll
        for (int kk = 0; kk < 16; kk++) {
            float a[8], b[4];
#pragma unroll
            for (int i = 0; i < 8; i++) a[i] = As[kk][ty * 8 + i];
#pragma unroll
            for (int j = 0; j < 4; j++) b[j] = Bs[kk][tx * 4 + j];
#pragma unroll
            for (int i = 0; i < 8; i++)
#pragma unroll
                for (int j = 0; j < 4; j++) acc[i][j] += a[i] * b[j];
        }
        __syncthreads();
    }
#pragma unroll
    for (int i = 0; i < 8; i++) {
        int r = row0 + ty * 8 + i;
#pragma unroll
        for (int j = 0; j < 4; j++) {
            int n = n0 + tx * 4 + j;
            if (n < N) C[(size_t)r * N + n] = acc[i][j];
        }
    }
}

__global__ void k_wloss(const float* __restrict__ W, float* __restrict__ C)
{
    __shared__ float sA[16][17];
    __shared__ float sB[16][17];
    int tx = threadIdx.x, ty = threadIdx.y;
    int i0 = blockIdx.y * 16, j0 = blockIdx.x * 16;
    float acc = 0.f;
    for (int k0 = 0; k0 < 800; k0 += 16) {
        sA[ty][tx] = (i0 + ty < MM) ? W[(size_t)(i0 + ty) * NN + k0 + tx] : 0.f;
        sB[ty][tx] = (j0 + ty < MM) ? W[(size_t)(j0 + ty) * NN + k0 + tx] : 0.f;
        __syncthreads();
#pragma unroll
        for (int kk = 0; kk < 16; kk++) acc += sA[ty][kk] * sB[tx][kk];
        __syncthreads();
    }
    int i = i0 + ty, j = j0 + tx;
    if (i < MM && j < MM) C[i * MM + j] = acc - (i == j ? 1.f : 0.f);
}

// ---------------- elementwise ----------------

__global__ void k_layer0(const float* __restrict__ PhiTb, float* __restrict__ X1,
                         float* __restrict__ zf,
                         const float* __restrict__ h_arr, const float* __restrict__ b2_arr)
{
    int i = blockIdx.x * blockDim.x + threadIdx.x;
    if (i >= NB) return;
    float h0 = h_arr[0], b2 = b2_arr[0];
    float x = h0 * PhiTb[i];
    X1[i] = x;
    zf[i] = h0 * b2 * x;
}

__global__ void k_hatx(const float* __restrict__ Xc, const float* __restrict__ Xp,
                       float* __restrict__ hx,
                       const float* __restrict__ tx_arr, int layer)
{
    int i = blockIdx.x * blockDim.x + threadIdx.x;
    if (i >= NB) return;
    float t = tx_arr[layer];
    float xc = Xc[i];
    hx[i] = xc + t * (xc - Xp[i]);
}

__global__ void k_xepi(const float* __restrict__ hx, const float* __restrict__ gm,
                       const float* __restrict__ PhiTb,
                       const float* __restrict__ Zg, const float* __restrict__ Lg,
                       const float* __restrict__ Zc, const float* __restrict__ Zp,
                       const float* __restrict__ Lz,
                       float* __restrict__ Xn, float* __restrict__ zf,
                       const float* __restrict__ b1a, const float* __restrict__ b2a,
                       const float* __restrict__ ha, const float* __restrict__ tza,
                       int layer)
{
    int i = blockIdx.x * blockDim.x + threadIdx.x;
    if (i >= NB) return;
    float b1 = b1a[layer], b2 = b2a[layer], hh = ha[layer], tz = tza[layer];
    float hxv = hx[i];
    float grad = PhiTb[i] - gm[i] + b1 * (Zg[i] - hxv) - Lg[i];
    float xn = hxv + hh * grad;
    Xn[i] = xn;
    float zc = Zc[i];
    float hz = zc + tz * (zc - Zp[i]);
    zf[i] = hz + hh * (Lz[i] + b2 * (xn - hz));
}

// ---------------- setup kernels ----------------

// zero the padding rows (r=0, r=21, c=0, c=43) of both NHWC buffers.
__global__ __launch_bounds__(128) void k_zeropad(float* __restrict__ a, float* __restrict__ b)
{
    int img = blockIdx.x, t = threadIdx.x;
    int row;
    if (t < 44) row = t;
    else if (t < 88) row = 924 + (t - 44);
    else { int j = t - 88; row = (1 + (j >> 1)) * 44 + ((j & 1) ? 43 : 0); }
    float4 z = make_float4(0.f, 0.f, 0.f, 0.f);
    float4* pa = (float4*)(a + (size_t)img * NHWC_STRIDE + row * 32);
    float4* pb = (float4*)(b + (size_t)img * NHWC_STRIDE + row * 32);
#pragma unroll
    for (int q = 0; q < 8; q++) { pa[q] = z; pb[q] = z; }
}

// weights [oc][ic][3][3] -> packed bf16 hi/lo [set][half][tap][icpair][BSTRIDE]
__global__ void k_wbf(const float* __restrict__ c2f, const float* __restrict__ c1b,
                      uint32_t* __restrict__ wpk)
{
    int i = blockIdx.x * blockDim.x + threadIdx.x;
    if (i >= 2 * BWORDS) return;
    int set = i / BWORDS, rem = i - set * BWORDS;
    int tap = rem / (16 * BSTRIDE), rem2 = rem - tap * (16 * BSTRIDE);
    int icp = rem2 / BSTRIDE, oc = rem2 - icp * BSTRIDE;
    const float* src = set ? c1b : c2f;
    uint32_t whi = 0u, wlo = 0u;
    if (oc < 32) {
        float w0 = src[oc * 288 + (2 * icp) * 9 + tap];
        float w1 = src[oc * 288 + (2 * icp + 1) * 9 + tap];
        __nv_bfloat16 h0 = __float2bfloat16_rn(w0), h1 = __float2bfloat16_rn(w1);
        __nv_bfloat16 l0 = __float2bfloat16_rn(w0 - __bfloat162float(h0));
        __nv_bfloat16 l1 = __float2bfloat16_rn(w1 - __bfloat162float(h1));
        whi = pkbf2(h0, h1);
        wlo = pkbf2(l0, l1);
    }
    int off = tap * (16 * BSTRIDE) + icp * BSTRIDE + oc;
    wpk[set * 2 * BWORDS + off] = whi;
    wpk[set * 2 * BWORDS + BWORDS + off] = wlo;
}

// ---------------- convolutions ----------------

// 1->32 channels, 3x3 SAME, relu. HW input -> NHWC output. One block per image.
__global__ __launch_bounds__(256) void conv1to32_nhwc(const float* __restrict__ zf,
                                                      const float* __restrict__ w,
                                                      float* __restrict__ out)
{
    __shared__ float sZ[NROWS];
    __shared__ float sW[288];    // [tap][oc]
    int img = blockIdx.x, tid = threadIdx.x;
    for (int i = tid; i < NROWS; i += 256) sZ[i] = 0.f;
    for (int i = tid; i < 288; i += 256) {
        int oc = i / 9, tap = i - oc * 9;
        sW[tap * 32 + oc] = w[i];
    }
    __syncthreads();
    const float* gin = zf + (size_t)img * NN;
    for (int i = tid; i < NN; i += 256) {
        int r = i / 40, c = i - r * 40;
        sZ[(r + 1) * 44 + c + 1] = gin[i];
    }
    __syncthreads();
    const int dtap[9] = {-45, -44, -43, -1, 0, 1, 43, 44, 45};
    float* gout = out + (size_t)img * NHWC_STRIDE;
    for (int p = tid; p < NN; p += 256) {
        int r = p / 40, c = p - r * 40;
        int pp = (r + 1) * 44 + (c + 1);
        float acc[32];
#pragma unroll
        for (int oc = 0; oc < 32; oc++) acc[oc] = 0.f;
#pragma unroll
        for (int t = 0; t < 9; t++) {
            float xv = sZ[pp + dtap[t]];
            const float* wt = sW + t * 32;
#pragma unroll
            for (int oc = 0; oc < 32; oc++) acc[oc] += wt[oc] * xv;
        }
        float4* ob = (float4*)(gout + pp * 32);
#pragma unroll
        for (int q = 0; q < 8; q++) {
            float4 v = make_float4(fmaxf(acc[q*4+0], 0.f), fmaxf(acc[q*4+1], 0.f),
                                   fmaxf(acc[q*4+2], 0.f), fmaxf(acc[q*4+3], 0.f));
            ob[q] = v;
        }
    }
}

// 32->32 channels, 3x3 SAME via mma.sync bf16 (3-pass hi/lo split).
// NHWC fp32 in/out. One CTA per image, 256 threads (8 warps).
// Conflict-free smem strides: ASTRIDE=20, BSTRIDE=40.
__global__ __launch_bounds__(256) void conv32_mma(const float* __restrict__ in,
                                                  const uint32_t* __restrict__ wpk,
                                                  float* __restrict__ outp,
                                                  const float* __restrict__ thr_arr,
                                                  int layer, int do_soft, int do_relu)
{
    extern __shared__ uint32_t smw[];
    uint32_t* sAhi = smw;                       // SROWS*ASTRIDE
    uint32_t* sAlo = smw + SROWS * ASTRIDE;
    uint32_t* sBhi = smw + 2 * SROWS * ASTRIDE; // BWORDS
    uint32_t* sBlo = sBhi + BWORDS;
    int img = blockIdx.x, tid = threadIdx.x;

    // zero guard rows [0,48) and [1016,1086)
    for (int i = tid; i < 48 * ASTRIDE; i += 256) { sAhi[i] = 0u; sAlo[i] = 0u; }
    for (int i = tid; i < 70 * ASTRIDE; i += 256) {
        sAhi[1016 * ASTRIDE + i] = 0u; sAlo[1016 * ASTRIDE + i] = 0u;
    }
    // weights
    for (int i = tid; i < BWORDS; i += 256) { sBhi[i] = wpk[i]; sBlo[i] = wpk[BWORDS + i]; }

    // main fill: fp32 NHWC -> (soft) -> bf16 hi/lo packed pairs
    float sthr = do_soft ? fabsf(thr_arr[layer]) : 0.f;
    const float4* g4 = (const float4*)(in + (size_t)img * NHWC_STRIDE);
    for (int i = tid; i < NROWS * 8; i += 256) {
        float4 v = g4[i];
        if (do_soft) {
#pragma unroll
            for (int j = 0; j < 4; j++) {
                float x = (&v.x)[j];
                float a = fabsf(x) - sthr;
                (&v.x)[j] = (a > 0.f) ? (x > 0.f ? a : -a) : 0.f;
            }
        }
        int row = i >> 3, qq = i & 7;
        int base = (SROW0 + row) * ASTRIDE + qq * 2;
        __nv_bfloat16 h0 = __float2bfloat16_rn(v.x);
        __nv_bfloat16 h1 = __float2bfloat16_rn(v.y);
        __nv_bfloat16 h2 = __float2bfloat16_rn(v.z);
        __nv_bfloat16 h3 = __float2bfloat16_rn(v.w);
        __nv_bfloat16 l0 = __float2bfloat16_rn(v.x - __bfloat162float(h0));
        __nv_bfloat16 l1 = __float2bfloat16_rn(v.y - __bfloat162float(h1));
        __nv_bfloat16 l2 = __float2bfloat16_rn(v.z - __bfloat162float(h2));
        __nv_bfloat16 l3 = __float2bfloat16_rn(v.w - __bfloat162float(h3));
        sAhi[base]     = pkbf2(h0, h1);
        sAhi[base + 1] = pkbf2(h2, h3);
        sAlo[base]     = pkbf2(l0, l1);
        sAlo[base + 1] = pkbf2(l2, l3);
    }
    __syncthreads();

    int warp = tid >> 5, lane = tid & 31;
    int q = lane >> 2, c = lane & 3;
    const int dtap[9] = {-45, -44, -43, -1, 0, 1, 43, 44, 45};
    float* gout = outp + (size_t)img * NHWC_STRIDE;

    for (int u = warp; u < 31; u += 8) {
        float acc[2][4][4];
#pragma unroll
        for (int s = 0; s < 2; s++)
#pragma unroll
            for (int o = 0; o < 4; o++)
#pragma unroll
                for (int j = 0; j < 4; j++) acc[s][o][j] = 0.f;

        int base_row = SROW0 + u * 32;
#pragma unroll
        for (int pass = 0; pass < 3; pass++) {
            const uint32_t* Aarr = (pass == 2) ? sAlo : sAhi;
            const uint32_t* Barr = (pass == 1) ? sBlo : sBhi;
#pragma unroll
            for (int ks = 0; ks < 18; ks++) {
                const int tap = ks >> 1;
                const int icb = (ks & 1) * 8;
                const uint32_t* Ap = Aarr + (base_row + dtap[tap] + q) * ASTRIDE + icb + c;
                uint32_t a0[4], a1[4];
                a0[0] = Ap[0];
                a0[1] = Ap[8 * ASTRIDE];
                a0[2] = Ap[4];
                a0[3] = Ap[8 * ASTRIDE + 4];
                a1[0] = Ap[16 * ASTRIDE];
                a1[1] = Ap[24 * ASTRIDE];
                a1[2] = Ap[16 * ASTRIDE + 4];
                a1[3] = Ap[24 * ASTRIDE + 4];
                const uint32_t* Bp = Barr + tap * (16 * BSTRIDE) + (icb + c) * BSTRIDE + q;
#pragma unroll
                for (int o = 0; o < 4; o++) {
                    uint32_t b0 = Bp[o * 8];
                    uint32_t b1 = Bp[4 * BSTRIDE + o * 8];
                    mma_bf16(acc[0][o], a0, b0, b1);
                    mma_bf16(acc[1][o], a1, b0, b1);
                }
            }
        }

        // epilogue: C frag (row=q/q+8, col=2c,2c+1 per octile)
#pragma unroll
        for (int s = 0; s < 2; s++) {
            int grow0 = u * 32 + s * 16 + q;
#pragma unroll
            for (int half = 0; half < 2; half++) {
                int grow = grow0 + half * 8;
                int rr = grow / 44, cc = grow - rr * 44;
                bool valid = (grow < NROWS) && rr >= 1 && rr <= 20 && cc >= 1 && cc <= 40;
                if (valid) {
                    float* ob = gout + grow * 32 + c * 2;
#pragma unroll
                    for (int o = 0; o < 4; o++) {
                        float x0 = acc[s][o][half * 2 + 0];
                        float x1 = acc[s][o][half * 2 + 1];
                        if (do_relu) { x0 = fmaxf(x0, 0.f); x1 = fmaxf(x1, 0.f); }
                        *(float2*)(ob + o * 8) = make_float2(x0, x1);
                    }
                }
            }
        }
    }
}

// 32->1 channels, 3x3 SAME, NHWC input. variant 0: Z_new + fused L-update.
// variant 1: (conv - z_flat) into syms.
__global__ __launch_bounds__(512) void conv32to1_nhwc(const float* __restrict__ in,
                                                      const float* __restrict__ w288,
                                                      float* __restrict__ outp,
                                                      const float* __restrict__ zf,
                                                      float* __restrict__ Ln,
                                                      const float* __restrict__ Lc,
                                                      const float* __restrict__ Lp,
                                                      const float* __restrict__ Xn,
                                                      const float* __restrict__ h_arr,
                                                      const float* __restrict__ b1_arr,
                                                      const float* __restrict__ tL_arr,
                                                      int layer, int variant)
{
    extern __shared__ float smemf[];
    float* sIn = smemf;                 // 968*32
    float* sW  = smemf + NROWS * 32;    // [tap][ic]
    int img = blockIdx.x, tid = threadIdx.x;
    const float4* g4 = (const float4*)(in + (size_t)img * NHWC_STRIDE);
    float4* s4 = (float4*)sIn;
    for (int i = tid; i < NROWS * 8; i += 512) s4[i] = g4[i];
    for (int i = tid; i < 288; i += 512) {
        int ic = i / 9, tap = i - ic * 9;
        sW[tap * 32 + ic] = w288[i];
    }
    __syncthreads();

    const int dtap[9] = {-45, -44, -43, -1, 0, 1, 43, 44, 45};
    size_t base = (size_t)img * NN;
    for (int p = tid; p < NN; p += 512) {
        int r = p / 40, c = p - r * 40;
        int pp = (r + 1) * 44 + (c + 1);
        float acc = 0.f;
#pragma unroll
        for (int t = 0; t < 9; t++) {
            const float4* a4 = (const float4*)(sIn + (pp + dtap[t]) * 32);
            const float4* wv = (const float4*)(sW + t * 32);
#pragma unroll
            for (int qq = 0; qq < 8; qq++) {
                float4 x = a4[qq], ww = wv[qq];
                acc += x.x * ww.x + x.y * ww.y + x.z * ww.z + x.w * ww.w;
            }
        }
        if (variant == 0) {
            outp[base + p] = acc;
            float lc = Lc[base + p], lp = Lp[base + p];
            float hatL = lc + tL_arr[layer] * (lc - lp);
            Ln[base + p] = hatL + h_arr[layer] * b1_arr[layer] * (Xn[base + p] - acc);
        } else {
            outp[base + p] = acc - zf[base + p];
        }
    }
}

// ---------------- host ----------------

extern "C" void kernel_launch(void* const* d_in, const int* in_sizes, int n_in,
                              void* d_out, int out_size)
{
    const float* y    = (const float*)d_in[0];
    const float* W    = (const float*)d_in[2];
    const float* beta1 = (const float*)d_in[3];
    const float* beta2 = (const float*)d_in[4];
    const float* h_   = (const float*)d_in[5];
    const float* sthr = (const float*)d_in[6];
    const float* thx  = (const float*)d_in[7];
    const float* thz  = (const float*)d_in[8];
    const float* thL  = (const float*)d_in[9];
    const float* c1f  = (const float*)d_in[10];
    const float* c2f  = (const float*)d_in[11];
    const float* c1b  = (const float*)d_in[12];
    const float* c2b  = (const float*)d_in[13];

    float* out = (float*)d_out;
    float* Zs = out;
    float* syms = out + (size_t)9 * NB;
    float* wlo = out + (size_t)18 * NB;

    float *pPhiTPhi, *pPhiTb, *pX, *pL, *pZero, *pZf, *pHx, *pGm, *pNA, *pNB;
    uint32_t* pWPK;
    cudaGetSymbolAddress((void**)&pPhiTPhi, g_PhiTPhi);
    cudaGetSymbolAddress((void**)&pPhiTb, g_PhiTb);
    cudaGetSymbolAddress((void**)&pX, g_Xbuf);
    cudaGetSymbolAddress((void**)&pL, g_Lbuf);
    cudaGetSymbolAddress((void**)&pZero, g_zerobuf);
    cudaGetSymbolAddress((void**)&pZf, g_zflat);
    cudaGetSymbolAddress((void**)&pHx, g_hatx);
    cudaGetSymbolAddress((void**)&pGm, g_gemm);
    cudaGetSymbolAddress((void**)&pNA, g_nA);
    cudaGetSymbolAddress((void**)&pNB, g_nB);
    cudaGetSymbolAddress((void**)&pWPK, g_wpk);

    const int SMMAW = (2 * SROWS * ASTRIDE + 2 * BWORDS) * 4;  // 219,840 B
    const int SM1   = (NROWS * 32 + 288) * 4;                  // 125,056 B
    cudaFuncSetAttribute(conv32_mma, cudaFuncAttributeMaxDynamicSharedMemorySize, SMMAW);
    cudaFuncSetAttribute(conv32to1_nhwc, cudaFuncAttributeMaxDynamicSharedMemorySize, SM1);

    cudaMemsetAsync(pZero, 0, (size_t)NB * 4);

    float* Xslot[2] = {pX, pX + NB};
    float* Lslot[2] = {pL, pL + NB};

    // setup
    gemm_AtB<<<dim3(13, 13), 256>>>(W, W, pPhiTPhi, MM, NN, NN);
    k_wloss<<<dim3(21, 21), dim3(16, 16)>>>(W, wlo);
    gemm_AB<<<dim3(13, 32), 256>>>(y, W, pPhiTb, BB, MM, NN);
    k_zeropad<<<BB, 128>>>(pNA, pNB);
    k_wbf<<<(2 * BWORDS + 255) / 256, 256>>>(c2f, c1b, pWPK);

    int xcur = 0, xprev = -1;
    int lcur = 0, lprev = -1;

    for (int i = 0; i < 9; i++) {
        float* Xn;
        if (i == 0) {
            Xn = Xslot[0];
            k_layer0<<<NB / 256, 256>>>(pPhiTb, Xn, pZf, h_, beta2);
            xcur = 0; xprev = -1;
        } else {
            const float* Xc = Xslot[xcur];
            const float* Xp = (xprev < 0) ? pZero : Xslot[xprev];
            const float* Lc_ = Lslot[lcur];
            const float* Zc = Zs + (size_t)(i - 1) * NB;
            const float* Zp = (i >= 2) ? Zs + (size_t)(i - 2) * NB : pZero;
            const float* Zg = (i >= 2) ? Zc : pZero;
            const float* Lg = (i >= 2) ? Lc_ : pZero;
            const float* Lz = (i >= 2) ? Lc_ : pZero;
            int xnew = (xprev < 0) ? 1 : xprev;
            Xn = Xslot[xnew];
            k_hatx<<<NB / 256, 256>>>(Xc, Xp, pHx, thx, i);
            gemm_AB<<<dim3(13, 32), 256>>>(pHx, pPhiTPhi, pGm, BB, NN, NN);
            k_xepi<<<NB / 256, 256>>>(pHx, pGm, pPhiTb, Zg, Lg, Zc, Zp, Lz,
                                      Xn, pZf, beta1, beta2, h_, thz, i);
            xprev = xcur; xcur = xnew;
        }

        // conv block (NHWC domain)
        conv1to32_nhwc<<<BB, 256>>>(pZf, c1f, pNA);
        conv32_mma<<<BB, 256, SMMAW>>>(pNA, pWPK,              pNB, sthr, i, 0, 0); // x_fwd
        conv32_mma<<<BB, 256, SMMAW>>>(pNB, pWPK + 2 * BWORDS, pNA, sthr, i, 1, 1); // t1
        {
            const float* Lc_ = (i == 0) ? pZero : Lslot[lcur];
            const float* Lp_ = (i == 0) ? pZero : ((lprev < 0) ? pZero : Lslot[lprev]);
            int lnew = (i == 0) ? 0 : ((lprev < 0) ? 1 : lprev);
            conv32to1_nhwc<<<BB, 512, SM1>>>(pNA, c2b, Zs + (size_t)i * NB, nullptr,
                                             Lslot[lnew], Lc_, Lp_, Xn,
                                             h_, beta1, thL, i, 0);
            if (i > 0) { lprev = lcur; lcur = lnew; }
            else { lcur = 0; lprev = -1; }
        }
        conv32_mma<<<BB, 256, SMMAW>>>(pNB, pWPK + 2 * BWORDS, pNA, sthr, i, 0, 1); // t2
        conv32to1_nhwc<<<BB, 512, SM1>>>(pNA, c2b, syms + (size_t)i * NB, pZf,
                                         nullptr, nullptr, nullptr, nullptr,
                                         h_, beta1, thL, i, 1);
    }
}